// round 6
// baseline (speedup 1.0000x reference)
#include <cuda_runtime.h>
#include <cuda_bf16.h>
#include <math.h>
#include <cstdint>

#define NN 35000
#define NM 80000
#define NBR 6
#define IND 128
#define HD 256
#define DEPTH 5
#define NNP 35072   // NN padded to 128-row tiles

// ---------------- scratch (__device__ globals; no allocs) ----------------
__device__ float g_rx2 [(size_t)NM*HD];
__device__ float g_fz  [(size_t)NM*HD];
__device__ float g_fh  [(size_t)NM*HD];
__device__ float g_hU  [(size_t)NM*HD];
__device__ float g_sumh[(size_t)NM*HD];
__device__ float g_hA  [(size_t)NM*HD];

// bf16 hi/lo plane buffers for GEMM A operands
__device__ __align__(16) __nv_bfloat16 g_fmh[(size_t)NM*IND];
__device__ __align__(16) __nv_bfloat16 g_fml[(size_t)NM*IND];
__device__ __align__(16) __nv_bfloat16 g_hh [(size_t)NM*HD];
__device__ __align__(16) __nv_bfloat16 g_hl [(size_t)NM*HD];
__device__ __align__(16) __nv_bfloat16 g_shh[(size_t)NM*HD];
__device__ __align__(16) __nv_bfloat16 g_shl[(size_t)NM*HD];
__device__ __align__(16) __nv_bfloat16 g_sgh[(size_t)NM*HD];
__device__ __align__(16) __nv_bfloat16 g_sgl[(size_t)NM*HD];
__device__ __align__(16) __nv_bfloat16 g_fnh[(size_t)NNP*IND];
__device__ __align__(16) __nv_bfloat16 g_fnl[(size_t)NNP*IND];
__device__ __align__(16) __nv_bfloat16 g_neh[(size_t)NNP*HD];
__device__ __align__(16) __nv_bfloat16 g_nel[(size_t)NNP*HD];

// transposed+split weights: [N=256, K] bf16, hi and lo planes
#define OFF_WZT 0
#define OFF_WHT 32768
#define OFF_WR  65536
#define OFF_WOT 98304
#define OFF_UR  131072
#define OFF_WZB 196608
#define OFF_WHB 262144
#define OFF_WOB 327680
__device__ __align__(16) __nv_bfloat16 g_bh[393216];
__device__ __align__(16) __nv_bfloat16 g_bl[393216];

__device__ __forceinline__ float sigm(float x){ return 1.0f/(1.0f+expf(-x)); }

// ---------------- mma / ldmatrix / cp.async helpers ----------------------
__device__ __forceinline__ uint32_t smem_addr(const void* p){
    return (uint32_t)__cvta_generic_to_shared(p);
}
__device__ __forceinline__ void ldsm4(uint32_t a, uint32_t& r0, uint32_t& r1,
                                      uint32_t& r2, uint32_t& r3){
    asm volatile("ldmatrix.sync.aligned.m8n8.x4.shared.b16 {%0,%1,%2,%3}, [%4];"
                 : "=r"(r0), "=r"(r1), "=r"(r2), "=r"(r3) : "r"(a));
}
__device__ __forceinline__ void mma16816(float* c, const uint32_t* a, const uint32_t* b){
    asm volatile(
        "mma.sync.aligned.m16n8k16.row.col.f32.bf16.bf16.f32 "
        "{%0,%1,%2,%3}, {%4,%5,%6,%7}, {%8,%9}, {%0,%1,%2,%3};"
        : "+f"(c[0]), "+f"(c[1]), "+f"(c[2]), "+f"(c[3])
        : "r"(a[0]), "r"(a[1]), "r"(a[2]), "r"(a[3]), "r"(b[0]), "r"(b[1]));
}
#define CPA16(dst, src) \
    asm volatile("cp.async.cg.shared.global [%0], [%1], 16;" :: "r"(dst), "l"(src))
#define CP_COMMIT() asm volatile("cp.async.commit_group;" ::: "memory")

// pack 2 floats into hi-bf16x2 and lo-bf16x2 words
__device__ __forceinline__ uint32_t split2(float x, float y, uint32_t& lo){
    __nv_bfloat16 hx = __float2bfloat16_rn(x);
    __nv_bfloat16 hy = __float2bfloat16_rn(y);
    __nv_bfloat16 lx = __float2bfloat16_rn(x - __bfloat162float(hx));
    __nv_bfloat16 ly = __float2bfloat16_rn(y - __bfloat162float(hy));
    lo = (uint32_t)__bfloat16_as_ushort(lx) | ((uint32_t)__bfloat16_as_ushort(ly) << 16);
    return (uint32_t)__bfloat16_as_ushort(hx) | ((uint32_t)__bfloat16_as_ushort(hy) << 16);
}
__device__ __forceinline__ void split4_store(float4 v, __nv_bfloat16* hi, __nv_bfloat16* lo,
                                             size_t elem_idx){
    uint32_t l0, l1;
    uint32_t h0 = split2(v.x, v.y, l0);
    uint32_t h1 = split2(v.z, v.w, l1);
    *(uint2*)(hi + elem_idx) = make_uint2(h0, h1);
    *(uint2*)(lo + elem_idx) = make_uint2(l0, l1);
}

// smem plane geometry: PADK bf16 per row (80B rows, conflict-free ldmatrix)
#define PADK 40
#define A_PLANE_B 10240            // 128*80
// stage layout: [A_hi][A_lo][B_hi][B_lo]; STAGE = 20480 + 2*NT*80

// ---- cp.async fill of one K-chunk (32 cols) into stage ----
template<int NT>
__device__ __forceinline__ void issue_chunk(
    const __nv_bfloat16* __restrict__ Ah, const __nv_bfloat16* __restrict__ Al, int K,
    const __nv_bfloat16* __restrict__ Bh, const __nv_bfloat16* __restrict__ Bl,
    uint32_t st, int tid, int rowBase, int colBase, int c)
{
    constexpr uint32_t SM_BL_ = 20480u + NT*80u;
    // A planes: 2 planes x 128 rows x 4 segs = 1024 ops
    #pragma unroll
    for (int i = 0; i < 2; ++i){
        int idx = tid + (i << 9);
        int plane = idx >> 9;
        int rem = idx & 511;
        int row = rem >> 2, seg = rem & 3;
        const __nv_bfloat16* src = (plane ? Al : Ah)
            + (size_t)(rowBase + row)*K + (c << 5) + (seg << 3);
        uint32_t dst = st + (plane ? 10240u : 0u) + row*80 + seg*16;
        CPA16(dst, src);
    }
    // B planes: 2 planes x NT rows x 4 segs
    #pragma unroll
    for (int i = 0; i < NT/64; ++i){
        int idx = tid + (i << 9);
        int plane = (idx >= NT*4) ? 1 : 0;
        int rem = idx - plane*NT*4;
        int row = rem >> 2, seg = rem & 3;
        const __nv_bfloat16* src = (plane ? Bl : Bh)
            + (size_t)(colBase + row)*K + (c << 5) + (seg << 3);
        uint32_t dst = st + (plane ? SM_BL_ : 20480u) + row*80 + seg*16;
        CPA16(dst, src);
    }
    CP_COMMIT();
}

// One 3-stage-pipelined GEMM phase: acc += split(A) @ B^T (rows [colBase,+NT) of B)
template<int NT>
__device__ __forceinline__ void run_phase(
    const __nv_bfloat16* __restrict__ Ah, const __nv_bfloat16* __restrict__ Al, int K,
    const __nv_bfloat16* __restrict__ Bh, const __nv_bfloat16* __restrict__ Bl,
    float* acc, char* sm, int tid, int rowBase, int colBase)
{
    constexpr int NFR = NT/32;
    constexpr uint32_t SM_BL_ = 20480u + NT*80u;
    constexpr uint32_t STAGE_ = 20480u + 2u*NT*80u;
    const int lane = tid & 31, wid = tid >> 5;
    const int wm = wid >> 2, wn = wid & 3;
    const int g = lane >> 3, r = lane & 7;
    const uint32_t sb = smem_addr(sm);
    const int nch = K >> 5;

    issue_chunk<NT>(Ah, Al, K, Bh, Bl, sb, tid, rowBase, colBase, 0);
    if (nch > 1) issue_chunk<NT>(Ah, Al, K, Bh, Bl, sb + STAGE_, tid, rowBase, colBase, 1);

    for (int c = 0; c < nch; ++c){
        if (c + 1 < nch) { asm volatile("cp.async.wait_group 1;" ::: "memory"); }
        else             { asm volatile("cp.async.wait_group 0;" ::: "memory"); }
        __syncthreads();   // stage c visible; all threads done computing stage c-1
        if (c + 2 < nch)
            issue_chunk<NT>(Ah, Al, K, Bh, Bl, sb + ((c+2)%3)*STAGE_,
                            tid, rowBase, colBase, c+2);
        const uint32_t st = sb + (c%3)*STAGE_;

        #pragma unroll
        for (int ki = 0; ki < 2; ++ki){
            uint32_t ah[2][4], al[2][4];
            {
                int arow = wm*32 + (g & 1)*8 + r;
                uint32_t off = (uint32_t)(arow*PADK + ki*16 + (g >> 1)*8) * 2;
                ldsm4(st + off,               ah[0][0], ah[0][1], ah[0][2], ah[0][3]);
                ldsm4(st + off + 16*PADK*2,   ah[1][0], ah[1][1], ah[1][2], ah[1][3]);
                ldsm4(st + 10240 + off,             al[0][0], al[0][1], al[0][2], al[0][3]);
                ldsm4(st + 10240 + off + 16*PADK*2, al[1][0], al[1][1], al[1][2], al[1][3]);
            }
            #pragma unroll
            for (int ng = 0; ng < NFR/4; ++ng){
                uint32_t bhf[4][2], blf[4][2];
                int nrow = wn*(NT/4) + ng*32 + (g >> 1)*8 + r;
                uint32_t off = (uint32_t)(nrow*PADK + ki*16 + (g & 1)*8) * 2;
                ldsm4(st + 20480 + off,             bhf[0][0], bhf[0][1], bhf[1][0], bhf[1][1]);
                ldsm4(st + 20480 + off + 16*PADK*2, bhf[2][0], bhf[2][1], bhf[3][0], bhf[3][1]);
                ldsm4(st + SM_BL_ + off,             blf[0][0], blf[0][1], blf[1][0], blf[1][1]);
                ldsm4(st + SM_BL_ + off + 16*PADK*2, blf[2][0], blf[2][1], blf[3][0], blf[3][1]);
                #pragma unroll
                for (int mi = 0; mi < 2; ++mi)
                    #pragma unroll
                    for (int j = 0; j < 4; ++j){
                        float* a = acc + (mi*NFR + ng*4 + j)*4;
                        mma16816(a, ah[mi], bhf[j]);
                        mma16816(a, ah[mi], blf[j]);
                        mma16816(a, al[mi], bhf[j]);
                    }
            }
        }
    }
    __syncthreads();   // protect stage buffers before any next phase
}

#define ZSTRIDE 130
#define SMEM_N256 (3*(20480 + 2*256*80))                  // 184320
#define SMEM_M1   (3*(20480 + 2*128*80) + 128*ZSTRIDE*4)  // 189440

// MODE 0 (NT=256): C = D + (e0 ? e0[col] : 0)
// MODE 1 (NT=128): z=sig(e0+D1), p=tanh(e1+D2); C=((1-z)*e2+z*p), row0=0;
//                  also writes Chi/Clo bf16 hi/lo planes of C
// MODE 2 (NT=256): D = A1@B1 + A2@B2; C = relu(D+e0[col])*e2[row], guarded rows
template<int MODE, int NT>
__global__ __launch_bounds__(512, 1)
void mma_gemm(const __nv_bfloat16* __restrict__ A1h, const __nv_bfloat16* __restrict__ A1l, int K1,
              const __nv_bfloat16* __restrict__ B1h, const __nv_bfloat16* __restrict__ B1l,
              const __nv_bfloat16* __restrict__ A2h, const __nv_bfloat16* __restrict__ A2l, int K2,
              const __nv_bfloat16* __restrict__ B2h, const __nv_bfloat16* __restrict__ B2l,
              int M,
              const float* __restrict__ e0, const float* __restrict__ e1,
              const float* __restrict__ e2,
              float* __restrict__ C,
              __nv_bfloat16* __restrict__ Chi, __nv_bfloat16* __restrict__ Clo)
{
    constexpr int NFR = NT/32;
    extern __shared__ char sm[];
    const int tid = threadIdx.x;
    int rowBase, colBase;
    if (NT == 256) { rowBase = (int)blockIdx.x << 7; colBase = 0; }
    else { rowBase = (int)(blockIdx.x >> 1) << 7; colBase = ((int)blockIdx.x & 1) << 7; }
    const int lane = tid & 31, wid = tid >> 5;
    const int wm = wid >> 2, wn = wid & 3;
    const int tq = lane >> 2, tr = lane & 3;

    float acc[2*NFR*4];
    #pragma unroll
    for (int i = 0; i < 2*NFR*4; ++i) acc[i] = 0.f;

    run_phase<NT>(A1h, A1l, K1, B1h, B1l, acc, sm, tid, rowBase, colBase);

    if (MODE == 0) {
        #pragma unroll
        for (int mi = 0; mi < 2; ++mi)
            #pragma unroll
            for (int ni = 0; ni < NFR; ++ni) {
                const float* a = acc + (mi*NFR + ni)*4;
                int gcol = colBase + wn*(NT/4) + ni*8 + tr*2;
                int r0 = rowBase + wm*32 + mi*16 + tq;
                float bx = 0.f, by = 0.f;
                if (e0) { float2 b = *(const float2*)&e0[gcol]; bx = b.x; by = b.y; }
                *(float2*)&C[(size_t)r0*HD + gcol]     = make_float2(a[0]+bx, a[1]+by);
                *(float2*)&C[(size_t)(r0+8)*HD + gcol] = make_float2(a[2]+bx, a[3]+by);
            }
    } else if (MODE == 1) {
        float* zbuf = (float*)(sm + 3*(20480 + 2*128*80));
        #pragma unroll
        for (int mi = 0; mi < 2; ++mi)
            #pragma unroll
            for (int ni = 0; ni < NFR; ++ni) {
                const float* a = acc + (mi*NFR + ni)*4;
                int lrow = wm*32 + mi*16 + tq;
                int lcol = wn*(NT/4) + ni*8 + tr*2;
                int r0 = rowBase + lrow;
                float2 ea = *(const float2*)&e0[(size_t)r0*HD + colBase + lcol];
                float2 eb = *(const float2*)&e0[(size_t)(r0+8)*HD + colBase + lcol];
                zbuf[lrow*ZSTRIDE + lcol]       = sigm(ea.x + a[0]);
                zbuf[lrow*ZSTRIDE + lcol + 1]   = sigm(ea.y + a[1]);
                zbuf[(lrow+8)*ZSTRIDE + lcol]   = sigm(eb.x + a[2]);
                zbuf[(lrow+8)*ZSTRIDE + lcol+1] = sigm(eb.y + a[3]);
            }
        #pragma unroll
        for (int i = 0; i < 2*NFR*4; ++i) acc[i] = 0.f;

        run_phase<NT>(A2h, A2l, K2, B2h, B2l, acc, sm, tid, rowBase, colBase);

        #pragma unroll
        for (int mi = 0; mi < 2; ++mi)
            #pragma unroll
            for (int ni = 0; ni < NFR; ++ni) {
                const float* a = acc + (mi*NFR + ni)*4;
                int lrow = wm*32 + mi*16 + tq;
                int lcol = wn*(NT/4) + ni*8 + tr*2;
                int r0 = rowBase + lrow;
                size_t o0 = (size_t)r0*HD + colBase + lcol;
                size_t o1 = (size_t)(r0+8)*HD + colBase + lcol;
                float2 ha = *(const float2*)&e1[o0];
                float2 hb = *(const float2*)&e1[o1];
                float2 sa = *(const float2*)&e2[o0];
                float2 sb = *(const float2*)&e2[o1];
                float z0 = zbuf[lrow*ZSTRIDE + lcol];
                float z1 = zbuf[lrow*ZSTRIDE + lcol + 1];
                float z2 = zbuf[(lrow+8)*ZSTRIDE + lcol];
                float z3 = zbuf[(lrow+8)*ZSTRIDE + lcol + 1];
                float p0 = tanhf(ha.x + a[0]);
                float p1 = tanhf(ha.y + a[1]);
                float p2 = tanhf(hb.x + a[2]);
                float p3 = tanhf(hb.y + a[3]);
                float2 u0 = make_float2((1.f - z0)*sa.x + z0*p0, (1.f - z1)*sa.y + z1*p1);
                float2 u1 = make_float2((1.f - z2)*sb.x + z2*p2, (1.f - z3)*sb.y + z3*p3);
                if (r0 == 0) u0 = make_float2(0.f, 0.f);   // null message row
                *(float2*)&C[o0] = u0;
                *(float2*)&C[o1] = u1;
                uint32_t l0, l1;
                uint32_t h0 = split2(u0.x, u0.y, l0);
                uint32_t h1 = split2(u1.x, u1.y, l1);
                *(uint32_t*)(Chi + o0) = h0;  *(uint32_t*)(Clo + o0) = l0;
                *(uint32_t*)(Chi + o1) = h1;  *(uint32_t*)(Clo + o1) = l1;
            }
    } else {
        run_phase<NT>(A2h, A2l, K2, B2h, B2l, acc, sm, tid, rowBase, colBase);
        #pragma unroll
        for (int mi = 0; mi < 2; ++mi)
            #pragma unroll
            for (int ni = 0; ni < NFR; ++ni) {
                const float* a = acc + (mi*NFR + ni)*4;
                int gcol = colBase + wn*(NT/4) + ni*8 + tr*2;
                int r0 = rowBase + wm*32 + mi*16 + tq;
                float2 b = *(const float2*)&e0[gcol];
                if (r0 < M) {
                    float m = e2[r0];
                    *(float2*)&C[(size_t)r0*HD + gcol] =
                        make_float2(fmaxf(a[0]+b.x, 0.f)*m, fmaxf(a[1]+b.y, 0.f)*m);
                }
                if (r0 + 8 < M) {
                    float m = e2[r0+8];
                    *(float2*)&C[(size_t)(r0+8)*HD + gcol] =
                        make_float2(fmaxf(a[2]+b.x, 0.f)*m, fmaxf(a[3]+b.y, 0.f)*m);
                }
            }
    }
}

// transpose + bf16 hi/lo split of W[K,256] -> out[N=256, K]
__global__ void prep_w(const float* __restrict__ W, __nv_bfloat16* __restrict__ oh,
                       __nv_bfloat16* __restrict__ ol, int K, int kshift)
{
    int i = blockIdx.x * blockDim.x + threadIdx.x;
    int k = i & (K - 1);
    int n = i >> kshift;
    float x = W[(size_t)k * HD + n];
    __nv_bfloat16 h = __float2bfloat16_rn(x);
    __nv_bfloat16 lo = __float2bfloat16_rn(x - __bfloat162float(h));
    oh[i] = h; ol[i] = lo;
}

// elementwise bf16 hi/lo split (row-major passthrough)
__global__ void prep_split(const float4* __restrict__ X, __nv_bfloat16* __restrict__ xh,
                           __nv_bfloat16* __restrict__ xl)
{
    size_t i = blockIdx.x*(size_t)blockDim.x + threadIdx.x;
    split4_store(X[i], xh, xl, i*4);
}

// Step 1 (h=0): h1 = sigmoid(fz)*tanh(fh), row 0 masked; also emit planes.
__global__ void first_step(const float4* __restrict__ fz, const float4* __restrict__ fh,
                           float4* __restrict__ h1,
                           __nv_bfloat16* __restrict__ hh, __nv_bfloat16* __restrict__ hl)
{
    size_t i = blockIdx.x*(size_t)blockDim.x + threadIdx.x;
    float4 z = fz[i], h = fh[i];
    float4 o;
    o.x = sigm(z.x)*tanhf(h.x);
    o.y = sigm(z.y)*tanhf(h.y);
    o.z = sigm(z.z)*tanhf(h.z);
    o.w = sigm(z.w)*tanhf(h.w);
    if (i < HD/4) o = make_float4(0.f,0.f,0.f,0.f);
    h1[i] = o;
    split4_store(o, hh, hl, i*4);
}

// gather: sum_h (fp32 + planes), sum_g (planes only)
__global__ void gather_msgs(const float* __restrict__ h, const float* __restrict__ hU,
                            const float* __restrict__ rx2, const int* __restrict__ bg,
                            float* __restrict__ sumh,
                            __nv_bfloat16* __restrict__ shh, __nv_bfloat16* __restrict__ shl,
                            __nv_bfloat16* __restrict__ sgh, __nv_bfloat16* __restrict__ sgl)
{
    __shared__ int s_nb[4][NBR];
    int e = blockIdx.x * 4 + threadIdx.y;
    if (threadIdx.x < NBR) s_nb[threadIdx.y][threadIdx.x] = bg[e*NBR + threadIdx.x];
    __syncthreads();
    int c = threadIdx.x << 2;
    size_t base = (size_t)e*HD + c;
    float4 rxv = *(const float4*)&rx2[base];
    float4 sh = make_float4(0.f,0.f,0.f,0.f);
    float4 sg = make_float4(0.f,0.f,0.f,0.f);
    #pragma unroll
    for (int j = 0; j < NBR; ++j) {
        size_t nb = (size_t)s_nb[threadIdx.y][j]*HD + c;
        float4 hv = *(const float4*)&h[nb];
        float4 hu = *(const float4*)&hU[nb];
        sh.x += hv.x; sh.y += hv.y; sh.z += hv.z; sh.w += hv.w;
        sg.x += sigm(rxv.x + hu.x) * hv.x;
        sg.y += sigm(rxv.y + hu.y) * hv.y;
        sg.z += sigm(rxv.z + hu.z) * hv.z;
        sg.w += sigm(rxv.w + hu.w) * hv.w;
    }
    *(float4*)&sumh[base] = sh;
    split4_store(sh, shh, shl, base);
    split4_store(sg, sgh, sgl, base);
}

// node gather: nei planes only
__global__ void gather_nodes(const float* __restrict__ h, const int* __restrict__ ag,
                             __nv_bfloat16* __restrict__ neh, __nv_bfloat16* __restrict__ nel)
{
    __shared__ int s_nb[4][NBR];
    int v = blockIdx.x * 4 + threadIdx.y;
    if (threadIdx.x < NBR) s_nb[threadIdx.y][threadIdx.x] = ag[v*NBR + threadIdx.x];
    __syncthreads();
    int c = threadIdx.x << 2;
    float4 s = make_float4(0.f,0.f,0.f,0.f);
    #pragma unroll
    for (int j = 0; j < NBR; ++j) {
        size_t nb = (size_t)s_nb[threadIdx.y][j]*HD + c;
        float4 hv = *(const float4*)&h[nb];
        s.x += hv.x; s.y += hv.y; s.z += hv.z; s.w += hv.w;
    }
    split4_store(s, neh, nel, (size_t)v*HD + c);
}

extern "C" void kernel_launch(void* const* d_in, const int* in_sizes, int n_in,
                              void* d_out, int out_size)
{
    const float* fnode  = (const float*)d_in[0];
    const float* fmess  = (const float*)d_in[1];
    const int*   agraph = (const int*)  d_in[2];
    const int*   bgraph = (const int*)  d_in[3];
    const float* mask   = (const float*)d_in[4];
    const float* W_z    = (const float*)d_in[5];
    const float* b_z    = (const float*)d_in[6];
    const float* W_r    = (const float*)d_in[7];
    const float* U_r    = (const float*)d_in[8];
    const float* b_ur   = (const float*)d_in[9];
    const float* W_h    = (const float*)d_in[10];
    const float* b_h    = (const float*)d_in[11];
    const float* W_o    = (const float*)d_in[12];
    const float* b_o    = (const float*)d_in[13];

    float* out_node = (float*)d_out;
    float* out_h    = out_node + (size_t)NN*HD;

    float *rx2, *fz, *fh, *hU, *sumh, *hA;
    __nv_bfloat16 *bh, *bl, *fmh, *fml, *hh, *hl, *shh, *shl, *sgh, *sgl, *fnh, *fnl, *neh, *nel;
    cudaGetSymbolAddress((void**)&rx2,  g_rx2);
    cudaGetSymbolAddress((void**)&fz,   g_fz);
    cudaGetSymbolAddress((void**)&fh,   g_fh);
    cudaGetSymbolAddress((void**)&hU,   g_hU);
    cudaGetSymbolAddress((void**)&sumh, g_sumh);
    cudaGetSymbolAddress((void**)&hA,   g_hA);
    cudaGetSymbolAddress((void**)&bh,   g_bh);
    cudaGetSymbolAddress((void**)&bl,   g_bl);
    cudaGetSymbolAddress((void**)&fmh,  g_fmh);
    cudaGetSymbolAddress((void**)&fml,  g_fml);
    cudaGetSymbolAddress((void**)&hh,   g_hh);
    cudaGetSymbolAddress((void**)&hl,   g_hl);
    cudaGetSymbolAddress((void**)&shh,  g_shh);
    cudaGetSymbolAddress((void**)&shl,  g_shl);
    cudaGetSymbolAddress((void**)&sgh,  g_sgh);
    cudaGetSymbolAddress((void**)&sgl,  g_sgl);
    cudaGetSymbolAddress((void**)&fnh,  g_fnh);
    cudaGetSymbolAddress((void**)&fnl,  g_fnl);
    cudaGetSymbolAddress((void**)&neh,  g_neh);
    cudaGetSymbolAddress((void**)&nel,  g_nel);

    cudaFuncSetAttribute(mma_gemm<0,256>, cudaFuncAttributeMaxDynamicSharedMemorySize, SMEM_N256);
    cudaFuncSetAttribute(mma_gemm<1,128>, cudaFuncAttributeMaxDynamicSharedMemorySize, SMEM_M1);
    cudaFuncSetAttribute(mma_gemm<2,256>, cudaFuncAttributeMaxDynamicSharedMemorySize, SMEM_N256);

    // ---- weight prep: transpose + hi/lo split ----
    prep_w<<<128, 256>>>(W_z,                  bh+OFF_WZT, bl+OFF_WZT, IND, 7);
    prep_w<<<128, 256>>>(W_h,                  bh+OFF_WHT, bl+OFF_WHT, IND, 7);
    prep_w<<<128, 256>>>(W_r,                  bh+OFF_WR,  bl+OFF_WR,  IND, 7);
    prep_w<<<128, 256>>>(W_o,                  bh+OFF_WOT, bl+OFF_WOT, IND, 7);
    prep_w<<<256, 256>>>(U_r,                  bh+OFF_UR,  bl+OFF_UR,  HD, 8);
    prep_w<<<256, 256>>>(W_z + (size_t)IND*HD, bh+OFF_WZB, bl+OFF_WZB, HD, 8);
    prep_w<<<256, 256>>>(W_h + (size_t)IND*HD, bh+OFF_WHB, bl+OFF_WHB, HD, 8);
    prep_w<<<256, 256>>>(W_o + (size_t)IND*HD, bh+OFF_WOB, bl+OFF_WOB, HD, 8);

    // ---- activation prep: fmess/fnode planes ----
    prep_split<<<(NM*IND/4)/256, 256>>>((const float4*)fmess, fmh, fml);
    prep_split<<<(NN*IND/4)/256, 256>>>((const float4*)fnode, fnh, fnl);

    const int gE256 = NM / 128;               // 625
    const int gE128 = (NM / 128) * 2;         // 1250
    const int gV    = NNP / 128;              // 274

    // loop-invariant GEMMs (bias folded via epilogue)
    mma_gemm<0,256><<<gE256, 512, SMEM_N256>>>(fmh, fml, IND, bh+OFF_WZT, bl+OFF_WZT,
        nullptr, nullptr, 0, nullptr, nullptr, NM, b_z,  nullptr, nullptr, fz,  nullptr, nullptr);
    mma_gemm<0,256><<<gE256, 512, SMEM_N256>>>(fmh, fml, IND, bh+OFF_WHT, bl+OFF_WHT,
        nullptr, nullptr, 0, nullptr, nullptr, NM, b_h,  nullptr, nullptr, fh,  nullptr, nullptr);
    mma_gemm<0,256><<<gE256, 512, SMEM_N256>>>(fmh, fml, IND, bh+OFF_WR, bl+OFF_WR,
        nullptr, nullptr, 0, nullptr, nullptr, NM, b_ur, nullptr, nullptr, rx2, nullptr, nullptr);

    // step 1 (h=0) is elementwise
    first_step<<<(NM*HD/4)/256, 256>>>((const float4*)fz, (const float4*)fh,
                                       (float4*)out_h, hh, hl);

    float* hc = out_h;
    float* hn = hA;
    for (int d = 1; d < DEPTH; ++d) {
        mma_gemm<0,256><<<gE256, 512, SMEM_N256>>>(hh, hl, HD, bh+OFF_UR, bl+OFF_UR,
            nullptr, nullptr, 0, nullptr, nullptr, NM, nullptr, nullptr, nullptr, hU,
            nullptr, nullptr);
        gather_msgs<<<NM/4, dim3(64,4)>>>(hc, hU, rx2, bgraph, sumh, shh, shl, sgh, sgl);
        mma_gemm<1,128><<<gE128, 512, SMEM_M1>>>(shh, shl, HD, bh+OFF_WZB, bl+OFF_WZB,
            sgh, sgl, HD, bh+OFF_WHB, bl+OFF_WHB, NM, fz, fh, sumh, hn, hh, hl);
        float* t = hc; hc = hn; hn = t;
    }

    gather_nodes<<<NN/4, dim3(64,4)>>>(hc, agraph, neh, nel);
    mma_gemm<2,256><<<gV, 512, SMEM_N256>>>(fnh, fnl, IND, bh+OFF_WOT, bl+OFF_WOT,
        neh, nel, HD, bh+OFF_WOB, bl+OFF_WOB, NN, b_o, nullptr, mask, out_node,
        nullptr, nullptr);
}

// round 7
// speedup vs baseline: 1.1100x; 1.1100x over previous
#include <cuda_runtime.h>
#include <cuda_bf16.h>
#include <math.h>
#include <cstdint>

#define NN 35000
#define NM 80000
#define NBR 6
#define IND 128
#define HD 256
#define DEPTH 5
#define NNP 35072

// ---------------- scratch (__device__ globals; no allocs) ----------------
__device__ float g_rx2 [(size_t)NM*HD];
__device__ float g_fz  [(size_t)NM*HD];
__device__ float g_fh  [(size_t)NM*HD];
__device__ float g_hU  [(size_t)NM*HD];
__device__ float g_sumh[(size_t)NM*HD];
__device__ float g_sumg[(size_t)NM*HD];
__device__ float g_hA  [(size_t)NM*HD];
__device__ float g_nei [(size_t)NNP*HD];

// transposed+split weights: [N=256, K] bf16, hi and lo planes
#define OFF_WZT 0
#define OFF_WHT 32768
#define OFF_WR  65536
#define OFF_WOT 98304
#define OFF_UR  131072
#define OFF_WZB 196608
#define OFF_WHB 262144
#define OFF_WOB 327680
__device__ __align__(16) __nv_bfloat16 g_bh[393216];
__device__ __align__(16) __nv_bfloat16 g_bl[393216];

__device__ __forceinline__ float sigm(float x){ return 1.0f/(1.0f+expf(-x)); }

// ---------------- mma / ldmatrix / cp.async helpers ----------------------
__device__ __forceinline__ uint32_t smem_addr(const void* p){
    return (uint32_t)__cvta_generic_to_shared(p);
}
__device__ __forceinline__ void ldsm4(uint32_t a, uint32_t& r0, uint32_t& r1,
                                      uint32_t& r2, uint32_t& r3){
    asm volatile("ldmatrix.sync.aligned.m8n8.x4.shared.b16 {%0,%1,%2,%3}, [%4];"
                 : "=r"(r0), "=r"(r1), "=r"(r2), "=r"(r3) : "r"(a));
}
__device__ __forceinline__ void mma16816(float* c, const uint32_t* a, const uint32_t* b){
    asm volatile(
        "mma.sync.aligned.m16n8k16.row.col.f32.bf16.bf16.f32 "
        "{%0,%1,%2,%3}, {%4,%5,%6,%7}, {%8,%9}, {%0,%1,%2,%3};"
        : "+f"(c[0]), "+f"(c[1]), "+f"(c[2]), "+f"(c[3])
        : "r"(a[0]), "r"(a[1]), "r"(a[2]), "r"(a[3]), "r"(b[0]), "r"(b[1]));
}
#define CPA16(dst, src) \
    asm volatile("cp.async.cg.shared.global [%0], [%1], 16;" :: "r"(dst), "l"(src))
#define CP_COMMIT() asm volatile("cp.async.commit_group;" ::: "memory")
#define CP_WAIT0()  asm volatile("cp.async.wait_group 0;" ::: "memory")

__device__ __forceinline__ void cvt_split8(float4 v0, float4 v1, uint4& hi, uint4& lo){
    float f[8] = {v0.x,v0.y,v0.z,v0.w,v1.x,v1.y,v1.z,v1.w};
    uint32_t hh[8], ll[8];
    #pragma unroll
    for (int j = 0; j < 8; ++j) {
        __nv_bfloat16 h = __float2bfloat16_rn(f[j]);
        float hf = __bfloat162float(h);
        __nv_bfloat16 l = __float2bfloat16_rn(f[j] - hf);
        hh[j] = (uint32_t)__bfloat16_as_ushort(h);
        ll[j] = (uint32_t)__bfloat16_as_ushort(l);
    }
    hi = make_uint4(hh[0]|(hh[1]<<16), hh[2]|(hh[3]<<16), hh[4]|(hh[5]<<16), hh[6]|(hh[7]<<16));
    lo = make_uint4(ll[0]|(ll[1]<<16), ll[2]|(ll[3]<<16), ll[4]|(ll[5]<<16), ll[6]|(ll[7]<<16));
}

// smem geometry: rows of PADK bf16 (80 B), chunk = 32 K-cols
#define PADK 40
// stage layout: [A1h][A1l]([A2h][A2l]) [B1h][B1l]([B2h][B2l])
// A plane = 10240 B; B plane = NT*80 B
// STAGE(NT,NA) = NA*20480 + NA*2*NT*80

// ---- pipelined dual/single GEMM phase; ACCUMULATES into acc ----
// acc layout: acc[((op*2 + mi)*NFR + ni)*4 + q]
template<int NT, int NA>
__device__ __forceinline__ void run_phase(
    const float* __restrict__ A1, const float* __restrict__ A2, int K,
    const __nv_bfloat16* __restrict__ B1h, const __nv_bfloat16* __restrict__ B1l,
    const __nv_bfloat16* __restrict__ B2h, const __nv_bfloat16* __restrict__ B2l,
    float* acc, char* sm, int tid, int rowBase, int colBase, int M)
{
    constexpr int NFR = NT/32;
    constexpr uint32_t A_BYTES = NA*20480u;
    constexpr uint32_t BPL = NT*80u;
    constexpr uint32_t STAGE_ = A_BYTES + NA*2u*BPL;
    const int lane = tid & 31, wid = tid >> 5;
    const int wm = wid >> 2, wn = wid & 3;
    const int g = lane >> 3, r = lane & 7;
    const uint32_t sb = smem_addr(sm);
    const int nch = K >> 5;

    // A fill mapping: NA*512 units of (op,row,seg8)
    int a_op[NA], a_row[NA], a_seg[NA];
    const float* a_src[NA];
    bool a_ok[NA];
    #pragma unroll
    for (int i = 0; i < NA; ++i){
        int idx = tid + (i << 9);
        a_op[i] = idx >> 9;
        int rem = idx & 511;
        a_row[i] = rem >> 2; a_seg[i] = rem & 3;
        int grow = rowBase + a_row[i];
        a_ok[i] = (grow < M);
        const float* Ab = (a_op[i] == 0) ? A1 : A2;
        a_src[i] = Ab + (size_t)grow*K + (a_seg[i] << 3);
    }

    // B fill mapping: 4 cp.async units per thread
    uint32_t b_dst[4]; const __nv_bfloat16* b_src[4];
    #pragma unroll
    for (int i = 0; i < 4; ++i){
        int idx = tid + (i << 9);                    // 0 .. NA*2*NT*4-1
        int op = idx / (NT*8);
        int rem = idx - op*(NT*8);
        int plane = rem / (NT*4);
        int rem2 = rem - plane*(NT*4);
        int row = rem2 >> 2, seg = rem2 & 3;
        const __nv_bfloat16* Bp = (op == 0) ? (plane ? B1l : B1h)
                                            : (plane ? B2l : B2h);
        b_src[i] = Bp + (size_t)(colBase + row)*K + (seg << 3);
        b_dst[i] = A_BYTES + (uint32_t)op*(2u*BPL) + (uint32_t)plane*BPL
                 + (uint32_t)row*80u + (uint32_t)seg*16u;
    }

    // ---- prologue: stage 0 ----
    {
        float4 v0[NA], v1[NA];
        #pragma unroll
        for (int i = 0; i < NA; ++i){
            v0[i] = make_float4(0.f,0.f,0.f,0.f); v1[i] = v0[i];
            if (a_ok[i]){ v0[i] = *(const float4*)a_src[i];
                          v1[i] = *(const float4*)(a_src[i] + 4); }
        }
        #pragma unroll
        for (int i = 0; i < 4; ++i) CPA16(sb + b_dst[i], b_src[i]);
        CP_COMMIT();
        #pragma unroll
        for (int i = 0; i < NA; ++i){
            uint4 hi, lo; cvt_split8(v0[i], v1[i], hi, lo);
            uint32_t ao = (uint32_t)a_op[i]*20480u + (uint32_t)a_row[i]*80u
                        + (uint32_t)a_seg[i]*16u;
            *(uint4*)(sm + ao)         = hi;
            *(uint4*)(sm + ao + 10240) = lo;
        }
        CP_WAIT0();
    }
    __syncthreads();

    for (int c = 0; c < nch; ++c){
        const uint32_t st = sb + (c & 1)*STAGE_;
        const int nc = c + 1;
        float4 v0[NA], v1[NA];
        if (nc < nch){
            #pragma unroll
            for (int i = 0; i < NA; ++i){
                v0[i] = make_float4(0.f,0.f,0.f,0.f); v1[i] = v0[i];
                if (a_ok[i]){
                    const float* p = a_src[i] + (nc << 5);
                    v0[i] = *(const float4*)p; v1[i] = *(const float4*)(p + 4);
                }
            }
            const uint32_t nst = sb + (nc & 1)*STAGE_;
            #pragma unroll
            for (int i = 0; i < 4; ++i) CPA16(nst + b_dst[i], b_src[i] + (nc << 5));
            CP_COMMIT();
        }

        // ---- compute on stage c ----
        #pragma unroll
        for (int op = 0; op < NA; ++op){
            const uint32_t aBase = st + (uint32_t)op*20480u;
            const uint32_t bBase = st + A_BYTES + (uint32_t)op*(2u*BPL);
            #pragma unroll
            for (int ki = 0; ki < 2; ++ki){
                uint32_t ah[2][4], al[2][4];
                {
                    int arow = wm*32 + (g & 1)*8 + r;
                    uint32_t off = (uint32_t)(arow*PADK + ki*16 + (g >> 1)*8) * 2;
                    ldsm4(aBase + off,                   ah[0][0], ah[0][1], ah[0][2], ah[0][3]);
                    ldsm4(aBase + off + 16*PADK*2,       ah[1][0], ah[1][1], ah[1][2], ah[1][3]);
                    ldsm4(aBase + 10240 + off,           al[0][0], al[0][1], al[0][2], al[0][3]);
                    ldsm4(aBase + 10240 + off + 16*PADK*2, al[1][0], al[1][1], al[1][2], al[1][3]);
                }
                #pragma unroll
                for (int ng = 0; ng < NFR/4; ++ng){
                    uint32_t bhf[4][2], blf[4][2];
                    int nrow = wn*(NT/4) + ng*32 + (g >> 1)*8 + r;
                    uint32_t off = (uint32_t)(nrow*PADK + ki*16 + (g & 1)*8) * 2;
                    ldsm4(bBase + off,                 bhf[0][0], bhf[0][1], bhf[1][0], bhf[1][1]);
                    ldsm4(bBase + off + 16*PADK*2,     bhf[2][0], bhf[2][1], bhf[3][0], bhf[3][1]);
                    ldsm4(bBase + BPL + off,             blf[0][0], blf[0][1], blf[1][0], blf[1][1]);
                    ldsm4(bBase + BPL + off + 16*PADK*2, blf[2][0], blf[2][1], blf[3][0], blf[3][1]);
                    #pragma unroll
                    for (int mi = 0; mi < 2; ++mi)
                        #pragma unroll
                        for (int j = 0; j < 4; ++j){
                            float* a = acc + (((op*2 + mi)*NFR) + ng*4 + j)*4;
                            mma16816(a, ah[mi], bhf[j]);
                            mma16816(a, ah[mi], blf[j]);
                            mma16816(a, al[mi], bhf[j]);
                        }
                }
            }
        }

        if (nc < nch){
            char* nsm = sm + (nc & 1)*STAGE_;
            #pragma unroll
            for (int i = 0; i < NA; ++i){
                uint4 hi, lo; cvt_split8(v0[i], v1[i], hi, lo);
                uint32_t ao = (uint32_t)a_op[i]*20480u + (uint32_t)a_row[i]*80u
                            + (uint32_t)a_seg[i]*16u;
                *(uint4*)(nsm + ao)         = hi;
                *(uint4*)(nsm + ao + 10240) = lo;
            }
            CP_WAIT0();
        }
        __syncthreads();
    }
}

#define SMEM0 (2*(20480 + 2*256*80))   // NT=256, NA=1 -> 122880
#define SMEM1 (2*(40960 + 4*128*80))   // NT=128, NA=2 -> 163840

// MODE 0 (NT=256,NA=1): C = D + (e0 ? e0[col] : 0)
// MODE 1 (NT=128,NA=2): z=sig(e0+D1), p=tanh(e1+D2); C=((1-z)*e2+z*p), row0=0
// MODE 2 (NT=256,NA=1 x2 phases): C = relu(D+e0[col])*e2[row], guarded rows
template<int MODE, int NT, int NA>
__global__ __launch_bounds__(512, 1)
void mma_gemm(const float* __restrict__ A1, int K1,
              const __nv_bfloat16* __restrict__ B1h, const __nv_bfloat16* __restrict__ B1l,
              const float* __restrict__ A2, int K2,
              const __nv_bfloat16* __restrict__ B2h, const __nv_bfloat16* __restrict__ B2l,
              int M,
              const float* __restrict__ e0, const float* __restrict__ e1,
              const float* __restrict__ e2, float* __restrict__ C)
{
    constexpr int NFR = NT/32;
    extern __shared__ char sm[];
    const int tid = threadIdx.x;
    int rowBase, colBase;
    if (NT == 256) { rowBase = (int)blockIdx.x << 7; colBase = 0; }
    else { rowBase = (int)(blockIdx.x >> 1) << 7; colBase = ((int)blockIdx.x & 1) << 7; }
    const int lane = tid & 31, wid = tid >> 5;
    const int wm = wid >> 2, wn = wid & 3;
    const int tq = lane >> 2, tr = lane & 3;

    float acc[NA*2*NFR*4];
    #pragma unroll
    for (int i = 0; i < NA*2*NFR*4; ++i) acc[i] = 0.f;

    if (MODE == 1) {
        run_phase<NT,2>(A1, A2, K1, B1h, B1l, B2h, B2l, acc, sm, tid, rowBase, colBase, M);
    } else {
        run_phase<NT,1>(A1, nullptr, K1, B1h, B1l, nullptr, nullptr,
                        acc, sm, tid, rowBase, colBase, M);
        if (MODE == 2)
            run_phase<NT,1>(A2, nullptr, K2, B2h, B2l, nullptr, nullptr,
                            acc, sm, tid, rowBase, colBase, M);
    }

    if (MODE == 0) {
        #pragma unroll
        for (int mi = 0; mi < 2; ++mi)
            #pragma unroll
            for (int ni = 0; ni < NFR; ++ni) {
                const float* a = acc + (mi*NFR + ni)*4;
                int gcol = colBase + wn*(NT/4) + ni*8 + tr*2;
                int r0 = rowBase + wm*32 + mi*16 + tq;
                float bx = 0.f, by = 0.f;
                if (e0) { float2 b = *(const float2*)&e0[gcol]; bx = b.x; by = b.y; }
                *(float2*)&C[(size_t)r0*HD + gcol]     = make_float2(a[0]+bx, a[1]+by);
                *(float2*)&C[(size_t)(r0+8)*HD + gcol] = make_float2(a[2]+bx, a[3]+by);
            }
    } else if (MODE == 1) {
        #pragma unroll
        for (int mi = 0; mi < 2; ++mi)
            #pragma unroll
            for (int ni = 0; ni < NFR; ++ni) {
                const float* a1 = acc + ((0*2 + mi)*NFR + ni)*4;
                const float* a2 = acc + ((1*2 + mi)*NFR + ni)*4;
                int lcol = wn*(NT/4) + ni*8 + tr*2;
                int r0 = rowBase + wm*32 + mi*16 + tq;
                size_t o0 = (size_t)r0*HD + colBase + lcol;
                size_t o1 = (size_t)(r0+8)*HD + colBase + lcol;
                float2 za = *(const float2*)&e0[o0];
                float2 zb = *(const float2*)&e0[o1];
                float2 ha = *(const float2*)&e1[o0];
                float2 hb = *(const float2*)&e1[o1];
                float2 sa = *(const float2*)&e2[o0];
                float2 sb = *(const float2*)&e2[o1];
                float z0 = sigm(za.x + a1[0]);
                float z1 = sigm(za.y + a1[1]);
                float z2 = sigm(zb.x + a1[2]);
                float z3 = sigm(zb.y + a1[3]);
                float p0 = tanhf(ha.x + a2[0]);
                float p1 = tanhf(ha.y + a2[1]);
                float p2 = tanhf(hb.x + a2[2]);
                float p3 = tanhf(hb.y + a2[3]);
                float2 u0 = make_float2((1.f - z0)*sa.x + z0*p0, (1.f - z1)*sa.y + z1*p1);
                float2 u1 = make_float2((1.f - z2)*sb.x + z2*p2, (1.f - z3)*sb.y + z3*p3);
                if (r0 == 0) u0 = make_float2(0.f, 0.f);   // null message row
                *(float2*)&C[o0] = u0;
                *(float2*)&C[o1] = u1;
            }
    } else {
        #pragma unroll
        for (int mi = 0; mi < 2; ++mi)
            #pragma unroll
            for (int ni = 0; ni < NFR; ++ni) {
                const float* a = acc + (mi*NFR + ni)*4;
                int gcol = colBase + wn*(NT/4) + ni*8 + tr*2;
                int r0 = rowBase + wm*32 + mi*16 + tq;
                float2 b = *(const float2*)&e0[gcol];
                if (r0 < M) {
                    float m = e2[r0];
                    *(float2*)&C[(size_t)r0*HD + gcol] =
                        make_float2(fmaxf(a[0]+b.x, 0.f)*m, fmaxf(a[1]+b.y, 0.f)*m);
                }
                if (r0 + 8 < M) {
                    float m = e2[r0+8];
                    *(float2*)&C[(size_t)(r0+8)*HD + gcol] =
                        make_float2(fmaxf(a[2]+b.x, 0.f)*m, fmaxf(a[3]+b.y, 0.f)*m);
                }
            }
    }
}

// transpose + bf16 hi/lo split of W[K,256] -> out[N=256, K]
__global__ void prep_w(const float* __restrict__ W, __nv_bfloat16* __restrict__ oh,
                       __nv_bfloat16* __restrict__ ol, int K, int kshift)
{
    int i = blockIdx.x * blockDim.x + threadIdx.x;
    int k = i & (K - 1);
    int n = i >> kshift;
    float x = W[(size_t)k * HD + n];
    __nv_bfloat16 h = __float2bfloat16_rn(x);
    __nv_bfloat16 lo = __float2bfloat16_rn(x - __bfloat162float(h));
    oh[i] = h; ol[i] = lo;
}

// Step 1 (h=0): h1 = sigmoid(fz)*tanh(fh), row 0 masked.
__global__ void first_step(const float4* __restrict__ fz, const float4* __restrict__ fh,
                           float4* __restrict__ h1)
{
    size_t i = blockIdx.x*(size_t)blockDim.x + threadIdx.x;
    float4 z = fz[i], h = fh[i];
    float4 o;
    o.x = sigm(z.x)*tanhf(h.x);
    o.y = sigm(z.y)*tanhf(h.y);
    o.z = sigm(z.z)*tanhf(h.z);
    o.w = sigm(z.w)*tanhf(h.w);
    if (i < HD/4) o = make_float4(0.f,0.f,0.f,0.f);
    h1[i] = o;
}

__global__ void gather_msgs(const float* __restrict__ h, const float* __restrict__ hU,
                            const float* __restrict__ rx2, const int* __restrict__ bg,
                            float* __restrict__ sumh, float* __restrict__ sumg)
{
    __shared__ int s_nb[4][NBR];
    int e = blockIdx.x * 4 + threadIdx.y;
    if (threadIdx.x < NBR) s_nb[threadIdx.y][threadIdx.x] = bg[e*NBR + threadIdx.x];
    __syncthreads();
    int c = threadIdx.x << 2;
    size_t base = (size_t)e*HD + c;
    float4 rxv = *(const float4*)&rx2[base];
    float4 sh = make_float4(0.f,0.f,0.f,0.f);
    float4 sg = make_float4(0.f,0.f,0.f,0.f);
    #pragma unroll
    for (int j = 0; j < NBR; ++j) {
        size_t nb = (size_t)s_nb[threadIdx.y][j]*HD + c;
        float4 hv = *(const float4*)&h[nb];
        float4 hu = *(const float4*)&hU[nb];
        sh.x += hv.x; sh.y += hv.y; sh.z += hv.z; sh.w += hv.w;
        sg.x += sigm(rxv.x + hu.x) * hv.x;
        sg.y += sigm(rxv.y + hu.y) * hv.y;
        sg.z += sigm(rxv.z + hu.z) * hv.z;
        sg.w += sigm(rxv.w + hu.w) * hv.w;
    }
    *(float4*)&sumh[base] = sh;
    *(float4*)&sumg[base] = sg;
}

__global__ void gather_nodes(const float* __restrict__ h, const int* __restrict__ ag,
                             float* __restrict__ nei)
{
    __shared__ int s_nb[4][NBR];
    int v = blockIdx.x * 4 + threadIdx.y;
    if (threadIdx.x < NBR) s_nb[threadIdx.y][threadIdx.x] = ag[v*NBR + threadIdx.x];
    __syncthreads();
    int c = threadIdx.x << 2;
    float4 s = make_float4(0.f,0.f,0.f,0.f);
    #pragma unroll
    for (int j = 0; j < NBR; ++j) {
        size_t nb = (size_t)s_nb[threadIdx.y][j]*HD + c;
        float4 hv = *(const float4*)&h[nb];
        s.x += hv.x; s.y += hv.y; s.z += hv.z; s.w += hv.w;
    }
    *(float4*)&nei[(size_t)v*HD + c] = s;
}

extern "C" void kernel_launch(void* const* d_in, const int* in_sizes, int n_in,
                              void* d_out, int out_size)
{
    const float* fnode  = (const float*)d_in[0];
    const float* fmess  = (const float*)d_in[1];
    const int*   agraph = (const int*)  d_in[2];
    const int*   bgraph = (const int*)  d_in[3];
    const float* mask   = (const float*)d_in[4];
    const float* W_z    = (const float*)d_in[5];
    const float* b_z    = (const float*)d_in[6];
    const float* W_r    = (const float*)d_in[7];
    const float* U_r    = (const float*)d_in[8];
    const float* b_ur   = (const float*)d_in[9];
    const float* W_h    = (const float*)d_in[10];
    const float* b_h    = (const float*)d_in[11];
    const float* W_o    = (const float*)d_in[12];
    const float* b_o    = (const float*)d_in[13];

    float* out_node = (float*)d_out;
    float* out_h    = out_node + (size_t)NN*HD;

    float *rx2, *fz, *fh, *hU, *sumh, *sumg, *hA, *nei;
    __nv_bfloat16 *bh, *bl;
    cudaGetSymbolAddress((void**)&rx2,  g_rx2);
    cudaGetSymbolAddress((void**)&fz,   g_fz);
    cudaGetSymbolAddress((void**)&fh,   g_fh);
    cudaGetSymbolAddress((void**)&hU,   g_hU);
    cudaGetSymbolAddress((void**)&sumh, g_sumh);
    cudaGetSymbolAddress((void**)&sumg, g_sumg);
    cudaGetSymbolAddress((void**)&hA,   g_hA);
    cudaGetSymbolAddress((void**)&nei,  g_nei);
    cudaGetSymbolAddress((void**)&bh,   g_bh);
    cudaGetSymbolAddress((void**)&bl,   g_bl);

    cudaFuncSetAttribute((const void*)mma_gemm<0,256,1>,
                         cudaFuncAttributeMaxDynamicSharedMemorySize, SMEM0);
    cudaFuncSetAttribute((const void*)mma_gemm<1,128,2>,
                         cudaFuncAttributeMaxDynamicSharedMemorySize, SMEM1);
    cudaFuncSetAttribute((const void*)mma_gemm<2,256,1>,
                         cudaFuncAttributeMaxDynamicSharedMemorySize, SMEM0);

    // ---- weight prep: transpose + hi/lo split ----
    prep_w<<<128, 256>>>(W_z,                  bh+OFF_WZT, bl+OFF_WZT, IND, 7);
    prep_w<<<128, 256>>>(W_h,                  bh+OFF_WHT, bl+OFF_WHT, IND, 7);
    prep_w<<<128, 256>>>(W_r,                  bh+OFF_WR,  bl+OFF_WR,  IND, 7);
    prep_w<<<128, 256>>>(W_o,                  bh+OFF_WOT, bl+OFF_WOT, IND, 7);
    prep_w<<<256, 256>>>(U_r,                  bh+OFF_UR,  bl+OFF_UR,  HD, 8);
    prep_w<<<256, 256>>>(W_z + (size_t)IND*HD, bh+OFF_WZB, bl+OFF_WZB, HD, 8);
    prep_w<<<256, 256>>>(W_h + (size_t)IND*HD, bh+OFF_WHB, bl+OFF_WHB, HD, 8);
    prep_w<<<256, 256>>>(W_o + (size_t)IND*HD, bh+OFF_WOB, bl+OFF_WOB, HD, 8);

    const int gE256 = NM / 128;               // 625
    const int gE128 = (NM / 128) * 2;         // 1250
    const int gV    = NNP / 128;              // 274

    // loop-invariant GEMMs (bias folded via epilogue); A read once per CTA
    mma_gemm<0,256,1><<<gE256, 512, SMEM0>>>(fmess, IND, bh+OFF_WZT, bl+OFF_WZT,
        nullptr, 0, nullptr, nullptr, NM, b_z,  nullptr, nullptr, fz);
    mma_gemm<0,256,1><<<gE256, 512, SMEM0>>>(fmess, IND, bh+OFF_WHT, bl+OFF_WHT,
        nullptr, 0, nullptr, nullptr, NM, b_h,  nullptr, nullptr, fh);
    mma_gemm<0,256,1><<<gE256, 512, SMEM0>>>(fmess, IND, bh+OFF_WR, bl+OFF_WR,
        nullptr, 0, nullptr, nullptr, NM, b_ur, nullptr, nullptr, rx2);

    // step 1 (h=0) is elementwise
    first_step<<<(NM*HD/4)/256, 256>>>((const float4*)fz, (const float4*)fh, (float4*)out_h);

    float* hc = out_h;
    float* hn = hA;
    for (int d = 1; d < DEPTH; ++d) {
        mma_gemm<0,256,1><<<gE256, 512, SMEM0>>>(hc, HD, bh+OFF_UR, bl+OFF_UR,
            nullptr, 0, nullptr, nullptr, NM, nullptr, nullptr, nullptr, hU);
        gather_msgs<<<NM/4, dim3(64,4)>>>(hc, hU, rx2, bgraph, sumh, sumg);
        mma_gemm<1,128,2><<<gE128, 512, SMEM1>>>(sumh, HD, bh+OFF_WZB, bl+OFF_WZB,
            sumg, HD, bh+OFF_WHB, bl+OFF_WHB, NM, fz, fh, sumh, hn);
        float* t = hc; hc = hn; hn = t;
    }

    gather_nodes<<<NN/4, dim3(64,4)>>>(hc, agraph, nei);
    mma_gemm<2,256,1><<<gV, 512, SMEM0>>>(fnode, IND, bh+OFF_WOT, bl+OFF_WOT,
        nei, HD, bh+OFF_WOB, bl+OFF_WOB, NN, b_o, nullptr, mask, out_node);
}